// round 16
// baseline (speedup 1.0000x reference)
#include <cuda_runtime.h>
#include <cuda_fp16.h>
#include <cstdint>

#define NN 50000
#define EE 800000
#define KD 128      // IN_C == HID_C
#define OC 64       // OUT_C
#define CAP 96      // per-node CSR bucket capacity (deg ~ Poisson(16))
#define LDH 136     // padded smem row length in halves (conflict-free)

// ---------------- scratch (device globals; no allocation allowed) ----------
// g_cur* are 0-based counters: zero-initialized at module load, and RESET to 0
// by the gathers after use -> every kernel_launch call sees zeros (no init kernel).
__device__ __align__(16) __half g_H1h[NN * KD];  // fp16 X*W1^T+b1
__device__ __align__(16) __half g_A1h[NN * KD];  // fp16 relu(aggregated)
__device__ __align__(16) __half g_H2h[NN * OC];  // fp16 A1*W2^T+b2
__device__ int g_cur1[NN], g_cur2[NN];
__device__ int g_csr1[NN * CAP], g_csr2[NN * CAP];

// ---------------- bucket-CSR build ------------------------------------------
// PDL sync at top: orders against the previous in-stream kernel (on graph
// replay, the prior iteration's gather2 -> cursor resets are visible).
__global__ __launch_bounds__(256) void k_fill(const int* __restrict__ ei) {
    cudaGridDependencySynchronize();
    int e = blockIdx.x * blockDim.x + threadIdx.x;
    if (e >= EE) return;
    int r = ei[e], c = ei[EE + e];
    int p1 = atomicAdd(&g_cur1[c], 1);
    g_csr1[c * CAP + p1] = r;
    int p2 = atomicAdd(&g_cur2[r], 1);
    g_csr2[r * CAP + p2] = c;
}

// ---------------- HMMA GEMM: C[M,BN] = fp16( A[M,128]*W[BN,128]^T + b ) -----
// SYNC_LATE=true (gemm1): reads only harness inputs -> sync AFTER the MMA
// mainloop; whole compute overlaps k_fill.
// SYNC_LATE=false (gemm2): stage W2 (A1h-independent) first, THEN sync, then
// stage A -> overlaps gather1's tail.
template<int BN, bool AHALF, bool SYNC_LATE>
__global__ __launch_bounds__(256)
void k_gemm(const void* __restrict__ Ain, const float* __restrict__ W,
            const float* __restrict__ bias, __half* __restrict__ C) {
    extern __shared__ __half sh[];
    __half* As = sh;              // [128][LDH]
    __half* Bs = sh + 128 * LDH;  // [BN][LDH]
    const int tid = threadIdx.x, wid = tid >> 5, lane = tid & 31;
    const int m0 = blockIdx.x * 128;

    // stage B (weights: never depends on predecessor output)
    for (int idx = tid; idx < BN * 32; idx += 256) {
        int n = idx >> 5, f = idx & 31;
        float4 v = *(const float4*)(W + (size_t)n * KD + f * 4);
        __half2 h0 = __floats2half2_rn(v.x, v.y);
        __half2 h1 = __floats2half2_rn(v.z, v.w);
        *(uint2*)(Bs + n * LDH + f * 4) =
            make_uint2(*(uint32_t*)&h0, *(uint32_t*)&h1);
    }

    if (!SYNC_LATE) cudaGridDependencySynchronize();   // gemm2: now needs A1h

    // stage A
    if (AHALF) {
        const __half* A = (const __half*)Ain;
        for (int idx = tid; idx < 128 * 16; idx += 256) {
            int m = idx >> 4, q = idx & 15;
            uint4 v = make_uint4(0u, 0u, 0u, 0u);
            if (m0 + m < NN) v = *(const uint4*)(A + (size_t)(m0 + m) * KD + q * 8);
            *(uint4*)(As + m * LDH + q * 8) = v;
        }
    } else {
        const float* A = (const float*)Ain;
        for (int idx = tid; idx < 128 * 32; idx += 256) {
            int m = idx >> 5, f = idx & 31;
            float4 v = make_float4(0.f, 0.f, 0.f, 0.f);
            if (m0 + m < NN) v = *(const float4*)(A + (size_t)(m0 + m) * KD + f * 4);
            __half2 h0 = __floats2half2_rn(v.x, v.y);
            __half2 h1 = __floats2half2_rn(v.z, v.w);
            *(uint2*)(As + m * LDH + f * 4) =
                make_uint2(*(uint32_t*)&h0, *(uint32_t*)&h1);
        }
    }
    __syncthreads();

    constexpr int NW = BN / 16;
    const int mw = (wid & 3) * 32;
    const int nw = (wid >> 2) * (BN / 2);
    const int g = lane >> 2, q4 = lane & 3;

    float acc[2][NW][4];
#pragma unroll
    for (int mi = 0; mi < 2; mi++)
#pragma unroll
        for (int nj = 0; nj < NW; nj++)
#pragma unroll
            for (int c = 0; c < 4; c++) acc[mi][nj][c] = 0.f;

#pragma unroll
    for (int ks = 0; ks < 8; ks++) {
        const int k2 = ks * 16 + q4 * 2;
        uint32_t a[2][4];
#pragma unroll
        for (int mi = 0; mi < 2; mi++) {
            const __half* ap = As + (mw + mi * 16 + g) * LDH;
            a[mi][0] = *(const uint32_t*)(ap + k2);
            a[mi][1] = *(const uint32_t*)(ap + 8 * LDH + k2);
            a[mi][2] = *(const uint32_t*)(ap + k2 + 8);
            a[mi][3] = *(const uint32_t*)(ap + 8 * LDH + k2 + 8);
        }
#pragma unroll
        for (int nj = 0; nj < NW; nj++) {
            const __half* bp = Bs + (nw + nj * 8 + g) * LDH;
            uint32_t b0 = *(const uint32_t*)(bp + k2);
            uint32_t b1 = *(const uint32_t*)(bp + k2 + 8);
#pragma unroll
            for (int mi = 0; mi < 2; mi++) {
                asm volatile(
                    "mma.sync.aligned.m16n8k16.row.col.f32.f16.f16.f32 "
                    "{%0,%1,%2,%3}, {%4,%5,%6,%7}, {%8,%9}, {%0,%1,%2,%3};"
                    : "+f"(acc[mi][nj][0]), "+f"(acc[mi][nj][1]),
                      "+f"(acc[mi][nj][2]), "+f"(acc[mi][nj][3])
                    : "r"(a[mi][0]), "r"(a[mi][1]), "r"(a[mi][2]), "r"(a[mi][3]),
                      "r"(b0), "r"(b1));
            }
        }
    }

    if (SYNC_LATE) cudaGridDependencySynchronize();    // gemm1: transitivity w/ fill

    float2 bv[NW];
#pragma unroll
    for (int nj = 0; nj < NW; nj++) {
        int c0 = nw + nj * 8 + q4 * 2;
        bv[nj] = make_float2(bias[c0], bias[c0 + 1]);
    }
#pragma unroll
    for (int mi = 0; mi < 2; mi++) {
        int r0 = m0 + mw + mi * 16 + g;
        int r1 = r0 + 8;
#pragma unroll
        for (int nj = 0; nj < NW; nj++) {
            int c0 = nw + nj * 8 + q4 * 2;
            if (r0 < NN) {
                __half2 h = __floats2half2_rn(acc[mi][nj][0] + bv[nj].x,
                                              acc[mi][nj][1] + bv[nj].y);
                *(__half2*)(C + (size_t)r0 * BN + c0) = h;
            }
            if (r1 < NN) {
                __half2 h = __floats2half2_rn(acc[mi][nj][2] + bv[nj].x,
                                              acc[mi][nj][3] + bv[nj].y);
                *(__half2*)(C + (size_t)r1 * BN + c0) = h;
            }
        }
    }
}

// ---------------- CSR gather (warp/node, shfl windows, HADD2 pairing) -------
__global__ __launch_bounds__(256) void k_gather1() {
    cudaGridDependencySynchronize();          // needs gemm1 (-> fill transitively)
    int v = blockIdx.x * 8 + (threadIdx.x >> 5);
    if (v >= NN) return;
    int lane = threadIdx.x & 31;
    const uint2* __restrict__ H = (const uint2*)g_H1h;
    int deg = g_cur1[v];                      // 0-based count
    if (lane == 0) g_cur1[v] = 0;             // reset for next call
    const int* __restrict__ src = g_csr1 + v * CAP;

    uint2 ps = H[(size_t)v * 32 + lane];
    float2 s0 = __half22float2(*(__half2*)&ps.x);
    float2 s1 = __half22float2(*(__half2*)&ps.y);
    float4 a0 = make_float4(s0.x, s0.y, s1.x, s1.y);
    float4 a1 = make_float4(0.f, 0.f, 0.f, 0.f);
    int j = 0;
    while (j < deg) {
        int cnt = deg - j; if (cnt > 32) cnt = 32;
        int u = (lane < cnt) ? src[j + lane] : 0;
        int k = 0;
        for (; k + 4 <= cnt; k += 4) {
            int u0 = __shfl_sync(0xffffffffu, u, k);
            int u1 = __shfl_sync(0xffffffffu, u, k + 1);
            int u2 = __shfl_sync(0xffffffffu, u, k + 2);
            int u3 = __shfl_sync(0xffffffffu, u, k + 3);
            uint2 p0 = H[(size_t)u0 * 32 + lane];
            uint2 p1 = H[(size_t)u1 * 32 + lane];
            uint2 p2 = H[(size_t)u2 * 32 + lane];
            uint2 p3 = H[(size_t)u3 * 32 + lane];
            __half2 hx0 = __hadd2(*(__half2*)&p0.x, *(__half2*)&p1.x);
            __half2 hy0 = __hadd2(*(__half2*)&p0.y, *(__half2*)&p1.y);
            __half2 hx1 = __hadd2(*(__half2*)&p2.x, *(__half2*)&p3.x);
            __half2 hy1 = __hadd2(*(__half2*)&p2.y, *(__half2*)&p3.y);
            float2 f0 = __half22float2(hx0);
            float2 f1 = __half22float2(hy0);
            float2 f2 = __half22float2(hx1);
            float2 f3 = __half22float2(hy1);
            a0.x += f0.x; a0.y += f0.y; a0.z += f1.x; a0.w += f1.y;
            a1.x += f2.x; a1.y += f2.y; a1.z += f3.x; a1.w += f3.y;
        }
        if (k + 2 <= cnt) {
            int u0 = __shfl_sync(0xffffffffu, u, k);
            int u1 = __shfl_sync(0xffffffffu, u, k + 1);
            uint2 p0 = H[(size_t)u0 * 32 + lane];
            uint2 p1 = H[(size_t)u1 * 32 + lane];
            __half2 hx = __hadd2(*(__half2*)&p0.x, *(__half2*)&p1.x);
            __half2 hy = __hadd2(*(__half2*)&p0.y, *(__half2*)&p1.y);
            float2 f0 = __half22float2(hx);
            float2 f1 = __half22float2(hy);
            a0.x += f0.x; a0.y += f0.y; a0.z += f1.x; a0.w += f1.y;
            k += 2;
        }
        if (k < cnt) {
            int u0 = __shfl_sync(0xffffffffu, u, k);
            uint2 p0 = H[(size_t)u0 * 32 + lane];
            float2 f0 = __half22float2(*(__half2*)&p0.x);
            float2 f1 = __half22float2(*(__half2*)&p0.y);
            a0.x += f0.x; a0.y += f0.y; a0.z += f1.x; a0.w += f1.y;
        }
        j += cnt;
    }
    float n = 1.0f / (float)(deg + 1);
    __half2 h0 = __floats2half2_rn(fmaxf(n * (a0.x + a1.x), 0.f),
                                   fmaxf(n * (a0.y + a1.y), 0.f));
    __half2 h1 = __floats2half2_rn(fmaxf(n * (a0.z + a1.z), 0.f),
                                   fmaxf(n * (a0.w + a1.w), 0.f));
    ((uint2*)g_A1h)[(size_t)v * 32 + lane] =
        make_uint2(*(uint32_t*)&h0, *(uint32_t*)&h1);
}

__global__ __launch_bounds__(256) void k_gather2(float* __restrict__ out) {
    cudaGridDependencySynchronize();          // needs gemm2
    int v = blockIdx.x * 8 + (threadIdx.x >> 5);
    if (v >= NN) return;
    int lane = threadIdx.x & 31;
    const __half2* __restrict__ H = (const __half2*)g_H2h;
    int deg = g_cur2[v];                      // 0-based count
    if (lane == 0) g_cur2[v] = 0;             // reset for next call
    const int* __restrict__ src = g_csr2 + v * CAP;

    float2 a0 = __half22float2(H[(size_t)v * 32 + lane]);
    float2 a1 = make_float2(0.f, 0.f);
    int j = 0;
    while (j < deg) {
        int cnt = deg - j; if (cnt > 32) cnt = 32;
        int u = (lane < cnt) ? src[j + lane] : 0;
        int k = 0;
        for (; k + 4 <= cnt; k += 4) {
            int u0 = __shfl_sync(0xffffffffu, u, k);
            int u1 = __shfl_sync(0xffffffffu, u, k + 1);
            int u2 = __shfl_sync(0xffffffffu, u, k + 2);
            int u3 = __shfl_sync(0xffffffffu, u, k + 3);
            __half2 p0 = H[(size_t)u0 * 32 + lane];
            __half2 p1 = H[(size_t)u1 * 32 + lane];
            __half2 p2 = H[(size_t)u2 * 32 + lane];
            __half2 p3 = H[(size_t)u3 * 32 + lane];
            float2 f0 = __half22float2(__hadd2(p0, p1));
            float2 f1 = __half22float2(__hadd2(p2, p3));
            a0.x += f0.x; a0.y += f0.y;
            a1.x += f1.x; a1.y += f1.y;
        }
        if (k + 2 <= cnt) {
            int u0 = __shfl_sync(0xffffffffu, u, k);
            int u1 = __shfl_sync(0xffffffffu, u, k + 1);
            __half2 p0 = H[(size_t)u0 * 32 + lane];
            __half2 p1 = H[(size_t)u1 * 32 + lane];
            float2 f0 = __half22float2(__hadd2(p0, p1));
            a0.x += f0.x; a0.y += f0.y;
            k += 2;
        }
        if (k < cnt) {
            int u0 = __shfl_sync(0xffffffffu, u, k);
            float2 f0 = __half22float2(H[(size_t)u0 * 32 + lane]);
            a0.x += f0.x; a0.y += f0.y;
        }
        j += cnt;
    }
    float n = 1.0f / (float)(deg + 1);
    float2 o;
    o.x = n * (a0.x + a1.x);
    o.y = n * (a0.y + a1.y);
    ((float2*)out)[(size_t)v * 32 + lane] = o;
}

// ---------------- launch: PDL-chained DAG (no init kernel) ------------------
extern "C" void kernel_launch(void* const* d_in, const int* in_sizes, int n_in,
                              void* d_out, int out_size) {
    const float* x  = (const float*)d_in[0];
    const int*   ei = (const int*)d_in[1];
    const float* W1 = (const float*)d_in[2];
    const float* b1 = (const float*)d_in[3];
    const float* W2 = (const float*)d_in[4];
    const float* b2 = (const float*)d_in[5];
    float* out = (float*)d_out;

    __half *pH1h, *pA1h, *pH2h;
    cudaGetSymbolAddress((void**)&pH1h, g_H1h);
    cudaGetSymbolAddress((void**)&pA1h, g_A1h);
    cudaGetSymbolAddress((void**)&pH2h, g_H2h);

    const int smem1 = (128 + 128) * LDH * 2;   // 69632
    const int smem2 = (128 + 64) * LDH * 2;    // 52224
    static bool s_attr_done = false;
    if (!s_attr_done) {
        cudaFuncSetAttribute((const void*)k_gemm<128, false, true>,
                             cudaFuncAttributeMaxDynamicSharedMemorySize, smem1);
        cudaFuncSetAttribute((const void*)k_gemm<64, true, false>,
                             cudaFuncAttributeMaxDynamicSharedMemorySize, smem2);
        s_attr_done = true;
    }

    cudaLaunchAttribute at[1];
    at[0].id = cudaLaunchAttributeProgrammaticStreamSerialization;
    at[0].val.programmaticStreamSerializationAllowed = 1;

    cudaLaunchConfig_t cfg{};
    cfg.blockDim = {256, 1, 1};
    cfg.stream = 0;
    cfg.attrs = at;
    cfg.numAttrs = 1;

    // fill -> gemm1(sync-late: overlaps fill) -> gather1(reset cur1)
    //      -> gemm2(B-stage overlaps gather1 tail) -> gather2(reset cur2)
    cfg.gridDim = {(EE + 255) / 256, 1, 1};
    cfg.dynamicSmemBytes = 0;
    cudaLaunchKernelEx(&cfg, k_fill, ei);

    cfg.gridDim = {(NN + 127) / 128, 1, 1};
    cfg.dynamicSmemBytes = smem1;
    cudaLaunchKernelEx(&cfg, k_gemm<128, false, true>,
                       (const void*)x, W1, b1, pH1h);

    cfg.gridDim = {(NN + 7) / 8, 1, 1};
    cfg.dynamicSmemBytes = 0;
    cudaLaunchKernelEx(&cfg, k_gather1);

    cfg.gridDim = {(NN + 127) / 128, 1, 1};
    cfg.dynamicSmemBytes = smem2;
    cudaLaunchKernelEx(&cfg, k_gemm<64, true, false>,
                       (const void*)pA1h, W2, b2, pH2h);

    cfg.gridDim = {(NN + 7) / 8, 1, 1};
    cfg.dynamicSmemBytes = 0;
    cudaLaunchKernelEx(&cfg, k_gather2, out);
}

// round 17
// speedup vs baseline: 2.5624x; 2.5624x over previous
#include <cuda_runtime.h>
#include <cuda_fp16.h>
#include <cstdint>

#define NN 50000
#define EE 800000
#define KD 128      // IN_C == HID_C
#define OC 64       // OUT_C
#define CAP 96      // per-node CSR bucket capacity (deg ~ Poisson(16))
#define LDH 136     // padded smem row length in halves (conflict-free)

// ---------------- scratch (device globals; no allocation allowed) ----------
__device__ __align__(16) __half g_H1h[NN * KD];  // fp16 X*W1^T+b1
__device__ __align__(16) __half g_A1h[NN * KD];  // fp16 relu(aggregated)
__device__ __align__(16) __half g_H2h[NN * OC];  // fp16 A1*W2^T+b2
__device__ int g_cur1[NN], g_cur2[NN];
__device__ int g_csr1[NN * CAP], g_csr2[NN * CAP];

// ---------------- bucket-CSR build ------------------------------------------
__global__ void k_init() {
    int i = blockIdx.x * blockDim.x + threadIdx.x;
    if (i < NN) { g_cur1[i] = i * CAP; g_cur2[i] = i * CAP; }
}

__global__ __launch_bounds__(256) void k_fill(const int* __restrict__ ei) {
    cudaGridDependencySynchronize();          // needs k_init
    int e = blockIdx.x * blockDim.x + threadIdx.x;
    if (e >= EE) return;
    int r = ei[e], c = ei[EE + e];
    int p1 = atomicAdd(&g_cur1[c], 1);
    g_csr1[p1] = r;
    int p2 = atomicAdd(&g_cur2[r], 1);
    g_csr2[p2] = c;
}

// ---------------- HMMA GEMM: C[M,BN] = fp16( A[M,128]*W[BN,128]^T + b ) -----
// SYNC_LATE=true: reads only harness inputs, so the grid-dependency sync sits
// AFTER the MMA mainloop -> whole compute overlaps the predecessor (k_fill).
template<int BN, bool AHALF, bool SYNC_LATE>
__global__ __launch_bounds__(256)
void k_gemm(const void* __restrict__ Ain, const float* __restrict__ W,
            const float* __restrict__ bias, __half* __restrict__ C) {
    extern __shared__ __half sh[];
    __half* As = sh;              // [128][LDH]
    __half* Bs = sh + 128 * LDH;  // [BN][LDH]
    const int tid = threadIdx.x, wid = tid >> 5, lane = tid & 31;
    const int m0 = blockIdx.x * 128;

    if (!SYNC_LATE) cudaGridDependencySynchronize();   // gemm2: needs A1h

    if (AHALF) {
        const __half* A = (const __half*)Ain;
        for (int idx = tid; idx < 128 * 16; idx += 256) {
            int m = idx >> 4, q = idx & 15;
            uint4 v = make_uint4(0u, 0u, 0u, 0u);
            if (m0 + m < NN) v = *(const uint4*)(A + (size_t)(m0 + m) * KD + q * 8);
            *(uint4*)(As + m * LDH + q * 8) = v;
        }
    } else {
        const float* A = (const float*)Ain;
        for (int idx = tid; idx < 128 * 32; idx += 256) {
            int m = idx >> 5, f = idx & 31;
            float4 v = make_float4(0.f, 0.f, 0.f, 0.f);
            if (m0 + m < NN) v = *(const float4*)(A + (size_t)(m0 + m) * KD + f * 4);
            __half2 h0 = __floats2half2_rn(v.x, v.y);
            __half2 h1 = __floats2half2_rn(v.z, v.w);
            *(uint2*)(As + m * LDH + f * 4) =
                make_uint2(*(uint32_t*)&h0, *(uint32_t*)&h1);
        }
    }
    for (int idx = tid; idx < BN * 32; idx += 256) {
        int n = idx >> 5, f = idx & 31;
        float4 v = *(const float4*)(W + (size_t)n * KD + f * 4);
        __half2 h0 = __floats2half2_rn(v.x, v.y);
        __half2 h1 = __floats2half2_rn(v.z, v.w);
        *(uint2*)(Bs + n * LDH + f * 4) =
            make_uint2(*(uint32_t*)&h0, *(uint32_t*)&h1);
    }
    __syncthreads();

    constexpr int NW = BN / 16;
    const int mw = (wid & 3) * 32;
    const int nw = (wid >> 2) * (BN / 2);
    const int g = lane >> 2, q4 = lane & 3;

    float acc[2][NW][4];
#pragma unroll
    for (int mi = 0; mi < 2; mi++)
#pragma unroll
        for (int nj = 0; nj < NW; nj++)
#pragma unroll
            for (int c = 0; c < 4; c++) acc[mi][nj][c] = 0.f;

#pragma unroll
    for (int ks = 0; ks < 8; ks++) {
        const int k2 = ks * 16 + q4 * 2;
        uint32_t a[2][4];
#pragma unroll
        for (int mi = 0; mi < 2; mi++) {
            const __half* ap = As + (mw + mi * 16 + g) * LDH;
            a[mi][0] = *(const uint32_t*)(ap + k2);
            a[mi][1] = *(const uint32_t*)(ap + 8 * LDH + k2);
            a[mi][2] = *(const uint32_t*)(ap + k2 + 8);
            a[mi][3] = *(const uint32_t*)(ap + 8 * LDH + k2 + 8);
        }
#pragma unroll
        for (int nj = 0; nj < NW; nj++) {
            const __half* bp = Bs + (nw + nj * 8 + g) * LDH;
            uint32_t b0 = *(const uint32_t*)(bp + k2);
            uint32_t b1 = *(const uint32_t*)(bp + k2 + 8);
#pragma unroll
            for (int mi = 0; mi < 2; mi++) {
                asm volatile(
                    "mma.sync.aligned.m16n8k16.row.col.f32.f16.f16.f32 "
                    "{%0,%1,%2,%3}, {%4,%5,%6,%7}, {%8,%9}, {%0,%1,%2,%3};"
                    : "+f"(acc[mi][nj][0]), "+f"(acc[mi][nj][1]),
                      "+f"(acc[mi][nj][2]), "+f"(acc[mi][nj][3])
                    : "r"(a[mi][0]), "r"(a[mi][1]), "r"(a[mi][2]), "r"(a[mi][3]),
                      "r"(b0), "r"(b1));
            }
        }
    }

    if (SYNC_LATE) cudaGridDependencySynchronize();    // gemm1: transitivity w/ fill

    float2 bv[NW];
#pragma unroll
    for (int nj = 0; nj < NW; nj++) {
        int c0 = nw + nj * 8 + q4 * 2;
        bv[nj] = make_float2(bias[c0], bias[c0 + 1]);
    }
#pragma unroll
    for (int mi = 0; mi < 2; mi++) {
        int r0 = m0 + mw + mi * 16 + g;
        int r1 = r0 + 8;
#pragma unroll
        for (int nj = 0; nj < NW; nj++) {
            int c0 = nw + nj * 8 + q4 * 2;
            if (r0 < NN) {
                __half2 h = __floats2half2_rn(acc[mi][nj][0] + bv[nj].x,
                                              acc[mi][nj][1] + bv[nj].y);
                *(__half2*)(C + (size_t)r0 * BN + c0) = h;
            }
            if (r1 < NN) {
                __half2 h = __floats2half2_rn(acc[mi][nj][2] + bv[nj].x,
                                              acc[mi][nj][3] + bv[nj].y);
                *(__half2*)(C + (size_t)r1 * BN + c0) = h;
            }
        }
    }
}

// ---------------- CSR gather (R9: warp/node, shfl windows, HADD2 pairing) ---
__global__ __launch_bounds__(256) void k_gather1() {
    cudaGridDependencySynchronize();          // needs gemm1 (-> fill transitively)
    int v = blockIdx.x * 8 + (threadIdx.x >> 5);
    if (v >= NN) return;
    int lane = threadIdx.x & 31;
    const uint2* __restrict__ H = (const uint2*)g_H1h;
    int deg = g_cur1[v] - v * CAP;
    const int* __restrict__ src = g_csr1 + v * CAP;

    uint2 ps = H[(size_t)v * 32 + lane];
    float2 s0 = __half22float2(*(__half2*)&ps.x);
    float2 s1 = __half22float2(*(__half2*)&ps.y);
    float4 a0 = make_float4(s0.x, s0.y, s1.x, s1.y);
    float4 a1 = make_float4(0.f, 0.f, 0.f, 0.f);
    int j = 0;
    while (j < deg) {
        int cnt = deg - j; if (cnt > 32) cnt = 32;
        int u = (lane < cnt) ? src[j + lane] : 0;
        int k = 0;
        for (; k + 4 <= cnt; k += 4) {
            int u0 = __shfl_sync(0xffffffffu, u, k);
            int u1 = __shfl_sync(0xffffffffu, u, k + 1);
            int u2 = __shfl_sync(0xffffffffu, u, k + 2);
            int u3 = __shfl_sync(0xffffffffu, u, k + 3);
            uint2 p0 = H[(size_t)u0 * 32 + lane];
            uint2 p1 = H[(size_t)u1 * 32 + lane];
            uint2 p2 = H[(size_t)u2 * 32 + lane];
            uint2 p3 = H[(size_t)u3 * 32 + lane];
            __half2 hx0 = __hadd2(*(__half2*)&p0.x, *(__half2*)&p1.x);
            __half2 hy0 = __hadd2(*(__half2*)&p0.y, *(__half2*)&p1.y);
            __half2 hx1 = __hadd2(*(__half2*)&p2.x, *(__half2*)&p3.x);
            __half2 hy1 = __hadd2(*(__half2*)&p2.y, *(__half2*)&p3.y);
            float2 f0 = __half22float2(hx0);
            float2 f1 = __half22float2(hy0);
            float2 f2 = __half22float2(hx1);
            float2 f3 = __half22float2(hy1);
            a0.x += f0.x; a0.y += f0.y; a0.z += f1.x; a0.w += f1.y;
            a1.x += f2.x; a1.y += f2.y; a1.z += f3.x; a1.w += f3.y;
        }
        if (k + 2 <= cnt) {
            int u0 = __shfl_sync(0xffffffffu, u, k);
            int u1 = __shfl_sync(0xffffffffu, u, k + 1);
            uint2 p0 = H[(size_t)u0 * 32 + lane];
            uint2 p1 = H[(size_t)u1 * 32 + lane];
            __half2 hx = __hadd2(*(__half2*)&p0.x, *(__half2*)&p1.x);
            __half2 hy = __hadd2(*(__half2*)&p0.y, *(__half2*)&p1.y);
            float2 f0 = __half22float2(hx);
            float2 f1 = __half22float2(hy);
            a0.x += f0.x; a0.y += f0.y; a0.z += f1.x; a0.w += f1.y;
            k += 2;
        }
        if (k < cnt) {
            int u0 = __shfl_sync(0xffffffffu, u, k);
            uint2 p0 = H[(size_t)u0 * 32 + lane];
            float2 f0 = __half22float2(*(__half2*)&p0.x);
            float2 f1 = __half22float2(*(__half2*)&p0.y);
            a0.x += f0.x; a0.y += f0.y; a0.z += f1.x; a0.w += f1.y;
        }
        j += cnt;
    }
    float n = 1.0f / (float)(deg + 1);
    __half2 h0 = __floats2half2_rn(fmaxf(n * (a0.x + a1.x), 0.f),
                                   fmaxf(n * (a0.y + a1.y), 0.f));
    __half2 h1 = __floats2half2_rn(fmaxf(n * (a0.z + a1.z), 0.f),
                                   fmaxf(n * (a0.w + a1.w), 0.f));
    ((uint2*)g_A1h)[(size_t)v * 32 + lane] =
        make_uint2(*(uint32_t*)&h0, *(uint32_t*)&h1);
}

__global__ __launch_bounds__(256) void k_gather2(float* __restrict__ out) {
    cudaGridDependencySynchronize();          // needs gemm2
    int v = blockIdx.x * 8 + (threadIdx.x >> 5);
    if (v >= NN) return;
    int lane = threadIdx.x & 31;
    const __half2* __restrict__ H = (const __half2*)g_H2h;
    int deg = g_cur2[v] - v * CAP;
    const int* __restrict__ src = g_csr2 + v * CAP;

    float2 a0 = __half22float2(H[(size_t)v * 32 + lane]);
    float2 a1 = make_float2(0.f, 0.f);
    int j = 0;
    while (j < deg) {
        int cnt = deg - j; if (cnt > 32) cnt = 32;
        int u = (lane < cnt) ? src[j + lane] : 0;
        int k = 0;
        for (; k + 4 <= cnt; k += 4) {
            int u0 = __shfl_sync(0xffffffffu, u, k);
            int u1 = __shfl_sync(0xffffffffu, u, k + 1);
            int u2 = __shfl_sync(0xffffffffu, u, k + 2);
            int u3 = __shfl_sync(0xffffffffu, u, k + 3);
            __half2 p0 = H[(size_t)u0 * 32 + lane];
            __half2 p1 = H[(size_t)u1 * 32 + lane];
            __half2 p2 = H[(size_t)u2 * 32 + lane];
            __half2 p3 = H[(size_t)u3 * 32 + lane];
            float2 f0 = __half22float2(__hadd2(p0, p1));
            float2 f1 = __half22float2(__hadd2(p2, p3));
            a0.x += f0.x; a0.y += f0.y;
            a1.x += f1.x; a1.y += f1.y;
        }
        if (k + 2 <= cnt) {
            int u0 = __shfl_sync(0xffffffffu, u, k);
            int u1 = __shfl_sync(0xffffffffu, u, k + 1);
            __half2 p0 = H[(size_t)u0 * 32 + lane];
            __half2 p1 = H[(size_t)u1 * 32 + lane];
            float2 f0 = __half22float2(__hadd2(p0, p1));
            a0.x += f0.x; a0.y += f0.y;
            k += 2;
        }
        if (k < cnt) {
            int u0 = __shfl_sync(0xffffffffu, u, k);
            float2 f0 = __half22float2(H[(size_t)u0 * 32 + lane]);
            a0.x += f0.x; a0.y += f0.y;
        }
        j += cnt;
    }
    float n = 1.0f / (float)(deg + 1);
    float2 o;
    o.x = n * (a0.x + a1.x);
    o.y = n * (a0.y + a1.y);
    ((float2*)out)[(size_t)v * 32 + lane] = o;
}

// ---------------- launch: PDL-chained DAG -----------------------------------
extern "C" void kernel_launch(void* const* d_in, const int* in_sizes, int n_in,
                              void* d_out, int out_size) {
    const float* x  = (const float*)d_in[0];
    const int*   ei = (const int*)d_in[1];
    const float* W1 = (const float*)d_in[2];
    const float* b1 = (const float*)d_in[3];
    const float* W2 = (const float*)d_in[4];
    const float* b2 = (const float*)d_in[5];
    float* out = (float*)d_out;

    __half *pH1h, *pA1h, *pH2h;
    cudaGetSymbolAddress((void**)&pH1h, g_H1h);
    cudaGetSymbolAddress((void**)&pA1h, g_A1h);
    cudaGetSymbolAddress((void**)&pH2h, g_H2h);

    const int smem1 = (128 + 128) * LDH * 2;   // 69632
    const int smem2 = (128 + 64) * LDH * 2;    // 52224
    static bool s_attr_done = false;
    if (!s_attr_done) {
        cudaFuncSetAttribute((const void*)k_gemm<128, false, true>,
                             cudaFuncAttributeMaxDynamicSharedMemorySize, smem1);
        cudaFuncSetAttribute((const void*)k_gemm<64, true, false>,
                             cudaFuncAttributeMaxDynamicSharedMemorySize, smem2);
        s_attr_done = true;
    }

    cudaLaunchAttribute at[1];
    at[0].id = cudaLaunchAttributeProgrammaticStreamSerialization;
    at[0].val.programmaticStreamSerializationAllowed = 1;

    cudaLaunchConfig_t cfg{};
    cfg.blockDim = {256, 1, 1};
    cfg.stream = 0;
    cfg.attrs = at;
    cfg.numAttrs = 1;

    // init -> fill -> gemm1(sync-late: overlaps fill) -> gather1 -> gemm2 -> gather2
    cfg.gridDim = {(NN + 255) / 256, 1, 1};
    cfg.dynamicSmemBytes = 0;
    cudaLaunchKernelEx(&cfg, k_init);

    cfg.gridDim = {(EE + 255) / 256, 1, 1};
    cudaLaunchKernelEx(&cfg, k_fill, ei);

    cfg.gridDim = {(NN + 127) / 128, 1, 1};
    cfg.dynamicSmemBytes = smem1;
    cudaLaunchKernelEx(&cfg, k_gemm<128, false, true>,
                       (const void*)x, W1, b1, pH1h);

    cfg.gridDim = {(NN + 7) / 8, 1, 1};
    cfg.dynamicSmemBytes = 0;
    cudaLaunchKernelEx(&cfg, k_gather1);

    cfg.gridDim = {(NN + 127) / 128, 1, 1};
    cfg.dynamicSmemBytes = smem2;
    cudaLaunchKernelEx(&cfg, k_gemm<64, true, false>,
                       (const void*)pA1h, W2, b2, pH2h);

    cfg.gridDim = {(NN + 7) / 8, 1, 1};
    cfg.dynamicSmemBytes = 0;
    cudaLaunchKernelEx(&cfg, k_gather2, out);
}